// round 16
// baseline (speedup 1.0000x reference)
#include <cuda_runtime.h>
#include <cuda_fp16.h>
#include <math.h>
#include <stdint.h>

#define B_SZ 2
#define L_SEQ 4352
#define DMODEL 768
#define DINNER 1536
#define DSTATE 128
#define NHEADS 24
#define HEADDIM 64
#define CONVDIM 1792
#define DPROJ 3352
#define IMG_N 4096
#define ROWS (B_SZ * L_SEQ)            // 8704
#define HEAD_ROWS (L_SEQ - IMG_N)      // 256
#define LN_EPS 1e-5f
#define K_CONV (25 * DMODEL)           // 19200
#define SEG 34
#define TSEG 128                       // 34*128 = 4352

// fp16 HMMA pipeline: BK=32 halfs, A smem stride 20 words, B stride 136 words
#define STG 5
#define AS_WORDS (128 * 20)
#define BS_WORDS (16 * 136)
#define SMEM_BYTES (STG * (AS_WORDS + BS_WORDS) * 4)      // 94720 -> 2 CTAs/SM

// 64-row tile variant (conv2d / out_proj)
#define AS64_WORDS (64 * 20)           // 1280
#define SMEM64_BYTES (STG * (AS64_WORDS + BS_WORDS) * 4)  // 69120 -> 3 CTAs/SM

// ---------------- static scratch ----------------
__device__ __align__(16) __half g_uh[ROWS * DMODEL];
__device__ __align__(16) float g_zx[ROWS * DPROJ];
__device__ __align__(16) float g_xbc[ROWS * CONVDIM];
__device__ float g_dt[ROWS * NHEADS];
__device__ float g_dA[ROWS * NHEADS];
__device__ float g_cums[ROWS * NHEADS];
__device__ __align__(16) float g_hseg[B_SZ * NHEADS * SEG * HEADDIM * DSTATE]; // 51MB
__device__ __align__(16) float g_y[ROWS * DINNER];
__device__ __align__(16) __half g_yh[ROWS * DINNER];
__device__ __align__(16) float g_h[ROWS * DMODEL];
__device__ __align__(16) __half g_imgh[B_SZ * IMG_N * DMODEL];
__device__ __align__(16) __half g_w2th[K_CONV * DMODEL];
__device__ __align__(16) uint32_t g_w2h[(K_CONV / 2) * DMODEL];
__device__ __align__(16) uint32_t g_w1h[(DMODEL / 2) * DPROJ];
__device__ __align__(16) uint32_t g_w3h[(DINNER / 2) * DMODEL];

// ---------------- helpers ----------------
__device__ __forceinline__ float blockSum256(float v) {
    __shared__ float sh[8];
    __syncthreads();
#pragma unroll
    for (int o = 16; o; o >>= 1) v += __shfl_xor_sync(0xffffffffu, v, o);
    if ((threadIdx.x & 31) == 0) sh[threadIdx.x >> 5] = v;
    __syncthreads();
    float tot = 0.f;
#pragma unroll
    for (int i = 0; i < 8; i++) tot += sh[i];
    return tot;
}

__device__ __forceinline__ void mma16(float* c, const uint32_t* a, const uint32_t* b) {
    asm("mma.sync.aligned.m16n8k16.row.col.f32.f16.f16.f32 "
        "{%0,%1,%2,%3},{%4,%5,%6,%7},{%8,%9},{%0,%1,%2,%3};"
        : "+f"(c[0]), "+f"(c[1]), "+f"(c[2]), "+f"(c[3])
        : "r"(a[0]), "r"(a[1]), "r"(a[2]), "r"(a[3]), "r"(b[0]), "r"(b[1]));
}

__device__ __forceinline__ void ldmatrix4(uint32_t* r, uint32_t addr) {
    asm volatile("ldmatrix.sync.aligned.m8n8.x4.shared.b16 {%0,%1,%2,%3}, [%4];"
                 : "=r"(r[0]), "=r"(r[1]), "=r"(r[2]), "=r"(r[3]) : "r"(addr));
}

__device__ __forceinline__ void cp16(uint32_t dst, const void* src, int srcbytes) {
    asm volatile("cp.async.cg.shared.global [%0], [%1], 16, %2;"
                 :: "r"(dst), "l"(src), "r"(srcbytes));
}
__device__ __forceinline__ void cp_commit() { asm volatile("cp.async.commit_group;"); }
__device__ __forceinline__ void cp_wait3() { asm volatile("cp.async.wait_group 3;"); }
__device__ __forceinline__ void cp_wait0() { asm volatile("cp.async.wait_group 0;"); }

// ---------------- pack fp32 [K][N] -> half2 k-pairs [K/2][N] ----------------
__global__ void pack_pairs_kernel(const float* __restrict__ src, uint32_t* __restrict__ dst,
                                  int K2, int N) {
    int i = blockIdx.x * 256 + threadIdx.x;
    if (i >= K2 * N) return;
    int k2 = i / N, n = i - k2 * N;
    __half lo = __float2half_rn(src[(size_t)(2 * k2) * N + n]);
    __half hi = __float2half_rn(src[(size_t)(2 * k2 + 1) * N + n]);
    dst[i] = (uint32_t)__half_as_ushort(lo) | ((uint32_t)__half_as_ushort(hi) << 16);
}

// ---------------- pack half [K][N] -> half2 k-pairs [K/2][N] ----------------
__global__ void pack_pairs_h_kernel(const __half* __restrict__ src, uint32_t* __restrict__ dst,
                                    int K2, int N) {
    int i = blockIdx.x * 256 + threadIdx.x;
    if (i >= K2 * N) return;
    int k2 = i / N, n = i - k2 * N;
    uint16_t lo = __half_as_ushort(src[(size_t)(2 * k2) * N + n]);
    uint16_t hi = __half_as_ushort(src[(size_t)(2 * k2 + 1) * N + n]);
    dst[i] = (uint32_t)lo | ((uint32_t)hi << 16);
}

// ---------------- conv2d weight transpose -> half ----------------
__global__ void wtrans_kernel(const float* __restrict__ w2) {
    __shared__ float tile[32][33];
    int k0 = blockIdx.x * 32, c0 = blockIdx.y * 32;
    int tx = threadIdx.x, ty = threadIdx.y;
#pragma unroll
    for (int i = 0; i < 4; i++)
        tile[ty + 8 * i][tx] = w2[(size_t)(c0 + ty + 8 * i) * K_CONV + k0 + tx];
    __syncthreads();
#pragma unroll
    for (int i = 0; i < 4; i++) {
        int k = k0 + ty + 8 * i;
        int tap = k % 25, ci = k / 25;
        g_w2th[(size_t)(tap * DMODEL + ci) * DMODEL + c0 + tx] =
            __float2half_rn(tile[tx][ty + 8 * i]);
    }
}

// ---------------- LayerNorm 1 ----------------
__global__ void ln1_kernel(const float* __restrict__ x, const float* __restrict__ w,
                           const float* __restrict__ b) {
    int row = blockIdx.x;
    int tid = threadIdx.x;
    const float* xr = x + row * DMODEL;
    float v0 = xr[tid], v1 = xr[tid + 256], v2 = xr[tid + 512];
    float mean = blockSum256(v0 + v1 + v2) * (1.f / 768.f);
    float d0 = v0 - mean, d1 = v1 - mean, d2 = v2 - mean;
    float var = blockSum256(d0 * d0 + d1 * d1 + d2 * d2) * (1.f / 768.f);
    float rs = rsqrtf(var + LN_EPS);
    __half* o = g_uh + (size_t)row * DMODEL;
    o[tid]       = __float2half_rn(d0 * rs * w[tid]       + b[tid]);
    o[tid + 256] = __float2half_rn(d1 * rs * w[tid + 256] + b[tid + 256]);
    o[tid + 512] = __float2half_rn(d2 * rs * w[tid + 512] + b[tid + 512]);
}

// ---------------- LayerNorm 2 ----------------
__global__ void ln2_kernel(const float* __restrict__ w, const float* __restrict__ b) {
    int m = blockIdx.x;
    int tid = threadIdx.x;
    int bb = m >> 12, pix = m & (IMG_N - 1);
    const float* xr = g_h + (size_t)(bb * L_SEQ + HEAD_ROWS + pix) * DMODEL;
    float v0 = xr[tid], v1 = xr[tid + 256], v2 = xr[tid + 512];
    float mean = blockSum256(v0 + v1 + v2) * (1.f / 768.f);
    float d0 = v0 - mean, d1 = v1 - mean, d2 = v2 - mean;
    float var = blockSum256(d0 * d0 + d1 * d1 + d2 * d2) * (1.f / 768.f);
    float rs = rsqrtf(var + LN_EPS);
    __half* o = g_imgh + (size_t)m * DMODEL;
    o[tid]       = __float2half_rn(d0 * rs * w[tid]       + b[tid]);
    o[tid + 256] = __float2half_rn(d1 * rs * w[tid + 256] + b[tid + 256]);
    o[tid + 512] = __float2half_rn(d2 * rs * w[tid + 512] + b[tid + 512]);
}

// ============================================================================
// fp16 HMMA GEMM, 128-row tile (in_proj), 5-stage cp.async (wait_group 3).
// ============================================================================
__global__ __launch_bounds__(256) void hgemm_cp_kernel(
    const __half* __restrict__ A, const uint32_t* __restrict__ Bp,
    float* __restrict__ C, int M, int N, int K) {
    extern __shared__ float smem[];
    float* AsB = smem;
    float* BsB = smem + STG * AS_WORDS;
    uint32_t as_base = (uint32_t)__cvta_generic_to_shared(AsB);
    uint32_t bs_base = (uint32_t)__cvta_generic_to_shared(BsB);
    int tid = threadIdx.x;
    int bm = blockIdx.y * 128, bn = blockIdx.x * 128;
    int ar = tid >> 1, p = tid & 1;
    int br = tid >> 4, bcn = (tid & 15) << 3;
    int lane = tid & 31, w = tid >> 5;
    int wm = w >> 2, wn = w & 3;
    int gid = lane >> 2, tig = lane & 3;

    int colb = bn + bcn;
    bool bok = colb < N;
    int bsrc = bok ? 16 : 0;
    const __half* aptr = A + (size_t)(bm + ar) * K + p * 16;
    const uint32_t* bptr = Bp + (size_t)br * N + (bok ? colb : 0);
    uint32_t asd0 = as_base + (uint32_t)(ar * 20 + p * 8) * 4;
    uint32_t bsd0 = bs_base + (uint32_t)(br * 136 + bcn) * 4;
    uint32_t a_lm = as_base + (uint32_t)(((wm * 64 + (lane & 15)) * 20) + ((lane >> 4) << 2)) * 4;

    float acc[4][4][4];
#pragma unroll
    for (int i = 0; i < 4; i++)
#pragma unroll
        for (int j = 0; j < 4; j++)
#pragma unroll
            for (int q = 0; q < 4; q++) acc[i][j][q] = 0.f;

    int ntiles = K >> 5;
#pragma unroll 1
    for (int s = 0; s < 4; ++s) {
        uint32_t asd = asd0 + s * AS_WORDS * 4;
        uint32_t bsd = bsd0 + s * BS_WORDS * 4;
        int ka = s << 5, kb = s << 4;
        cp16(asd, aptr + ka, 16);
        cp16(asd + 16, aptr + ka + 8, 16);
        cp16(bsd, bptr + (size_t)kb * N, bsrc);
        cp16(bsd + 16, bptr + (size_t)kb * N + 4, bsrc);
        cp_commit();
    }

    int islot = 4, cslot = 0;
    for (int kt = 0; kt < ntiles; ++kt) {
        cp_wait3();
        __syncthreads();
        if (kt + 4 < ntiles) {
            uint32_t asd = asd0 + islot * AS_WORDS * 4;
            uint32_t bsd = bsd0 + islot * BS_WORDS * 4;
            int ka = (kt + 4) << 5, kb = (kt + 4) << 4;
            cp16(asd, aptr + ka, 16);
            cp16(asd + 16, aptr + ka + 8, 16);
            cp16(bsd, bptr + (size_t)kb * N, bsrc);
            cp16(bsd + 16, bptr + (size_t)kb * N + 4, bsrc);
        }
        cp_commit();
        if (++islot == STG) islot = 0;
        uint32_t a_lm_s = a_lm + cslot * AS_WORDS * 4;
        const uint32_t* Bsb = (const uint32_t*)(BsB + cslot * BS_WORDS);
#pragma unroll
        for (int ks = 0; ks < 2; ++ks) {
            int k8 = ks * 8;
            uint32_t af[4][4], bf[4][2];
#pragma unroll
            for (int tm = 0; tm < 4; tm++)
                ldmatrix4(af[tm], a_lm_s + (uint32_t)(tm * 320 + k8) * 4);
#pragma unroll
            for (int tn = 0; tn < 4; tn++) {
                int cl = wn * 32 + tn * 8 + gid;
                bf[tn][0] = Bsb[(k8 + tig) * 136 + cl];
                bf[tn][1] = Bsb[(k8 + tig + 4) * 136 + cl];
            }
#pragma unroll
            for (int tm = 0; tm < 4; tm++)
#pragma unroll
                for (int tn = 0; tn < 4; tn++)
                    mma16(acc[tm][tn], af[tm], bf[tn]);
        }
        if (++cslot == STG) cslot = 0;
    }
    cp_wait0();
#pragma unroll
    for (int tm = 0; tm < 4; tm++) {
        int r0 = bm + wm * 64 + tm * 16 + gid;
#pragma unroll
        for (int tn = 0; tn < 4; tn++) {
            int c = bn + wn * 32 + tn * 8 + tig * 2;
            if (c < N) {
                *(float2*)&C[(size_t)r0 * N + c]       = make_float2(acc[tm][tn][0], acc[tm][tn][1]);
                *(float2*)&C[(size_t)(r0 + 8) * N + c] = make_float2(acc[tm][tn][2], acc[tm][tn][3]);
            }
        }
    }
}

// ============================================================================
// fp16 HMMA GEMM, 64-row tile (out_proj), 5-stage.
// ============================================================================
__global__ __launch_bounds__(256) void hgemm64_cp_kernel(
    const __half* __restrict__ A, const uint32_t* __restrict__ Bp,
    float* __restrict__ C, int M, int N, int K) {
    extern __shared__ float smem[];
    float* AsB = smem;
    float* BsB = smem + STG * AS64_WORDS;
    uint32_t as_base = (uint32_t)__cvta_generic_to_shared(AsB);
    uint32_t bs_base = (uint32_t)__cvta_generic_to_shared(BsB);
    int tid = threadIdx.x;
    int bm = blockIdx.y * 64, bn = blockIdx.x * 128;
    int ar = tid >> 2, q = tid & 3;
    int br = tid >> 4, bcn = (tid & 15) << 3;
    int lane = tid & 31, w = tid >> 5;
    int wm = w >> 2, wn = w & 3;
    int gid = lane >> 2, tig = lane & 3;

    int colb = bn + bcn;
    bool bok = colb < N;
    int bsrc = bok ? 16 : 0;
    const __half* aptr = A + (size_t)(bm + ar) * K + q * 8;
    const uint32_t* bptr = Bp + (size_t)br * N + (bok ? colb : 0);
    uint32_t asd0 = as_base + (uint32_t)(ar * 20 + q * 4) * 4;
    uint32_t bsd0 = bs_base + (uint32_t)(br * 136 + bcn) * 4;
    uint32_t a_lm = as_base + (uint32_t)(((wm * 32 + (lane & 15)) * 20) + ((lane >> 4) << 2)) * 4;

    float acc[2][4][4];
#pragma unroll
    for (int i = 0; i < 2; i++)
#pragma unroll
        for (int j = 0; j < 4; j++)
#pragma unroll
            for (int qq = 0; qq < 4; qq++) acc[i][j][qq] = 0.f;

    int ntiles = K >> 5;
#pragma unroll 1
    for (int s = 0; s < 4; ++s) {
        uint32_t asd = asd0 + s * AS64_WORDS * 4;
        uint32_t bsd = bsd0 + s * BS_WORDS * 4;
        int ka = s << 5, kb = s << 4;
        cp16(asd, aptr + ka, 16);
        cp16(bsd, bptr + (size_t)kb * N, bsrc);
        cp16(bsd + 16, bptr + (size_t)kb * N + 4, bsrc);
        cp_commit();
    }

    int islot = 4, cslot = 0;
    for (int kt = 0; kt < ntiles; ++kt) {
        cp_wait3();
        __syncthreads();
        if (kt + 4 < ntiles) {
            uint32_t asd = asd0 + islot * AS64_WORDS * 4;
            uint32_t bsd = bsd0 + islot * BS_WORDS * 4;
            int ka = (kt + 4) << 5, kb = (kt + 4) << 4;
            cp16(asd, aptr + ka, 16);
            cp16(bsd, bptr + (size_t)kb * N, bsrc);
            cp16(bsd + 16, bptr + (size_t)kb * N + 4, bsrc);
        }
        cp_commit();
        if (++islot == STG) islot = 0;
        uint32_t a_lm_s = a_lm + cslot * AS64_WORDS * 4;
        const uint32_t* Bsb = (const uint32_t*)(BsB + cslot * BS_WORDS);
#pragma unroll
        for (int ks = 0; ks < 2; ++ks) {
            int k8 = ks * 8;
            uint32_t af[2][4], bf[4][2];
#pragma unroll
            for (int tm = 0; tm < 2; tm++)
                ldmatrix4(af[tm], a_lm_s + (uint32_t)(tm * 320 + k8) * 4);
#pragma unroll
            for (int tn = 0; tn < 4; tn++) {
                int cl = wn * 32 + tn * 8 + gid;
                bf[tn][0] = Bsb[(k8 + tig) * 136 + cl];
                bf[tn][1] = Bsb[(k8 + tig + 4) * 136 + cl];
            }
#pragma unroll
            for (int tm = 0; tm < 2; tm++)
#pragma unroll
                for (int tn = 0; tn < 4; tn++)
                    mma16(acc[tm][tn], af[tm], bf[tn]);
        }
        if (++cslot == STG) cslot = 0;
    }
    cp_wait0();
#pragma unroll
    for (int tm = 0; tm < 2; tm++) {
        int r0 = bm + wm * 32 + tm * 16 + gid;
#pragma unroll
        for (int tn = 0; tn < 4; tn++) {
            int c = bn + wn * 32 + tn * 8 + tig * 2;
            if (c < N) {
                *(float2*)&C[(size_t)r0 * N + c]       = make_float2(acc[tm][tn][0], acc[tm][tn][1]);
                *(float2*)&C[(size_t)(r0 + 8) * N + c] = make_float2(acc[tm][tn][2], acc[tm][tn][3]);
            }
        }
    }
}

// ============================================================================
// conv2d 5x5 SAME implicit GEMM, 64-row tile, 5-stage + bias + residual.
// ============================================================================
__global__ __launch_bounds__(256) void conv2d_hm_kernel(
    const float* __restrict__ x, const float* __restrict__ bias2,
    float* __restrict__ out) {
    extern __shared__ float smem[];
    float* AsB = smem;
    float* BsB = smem + STG * AS64_WORDS;
    uint32_t as_base = (uint32_t)__cvta_generic_to_shared(AsB);
    uint32_t bs_base = (uint32_t)__cvta_generic_to_shared(BsB);
    int tid = threadIdx.x;
    int bm = blockIdx.y * 64, bn = blockIdx.x * 128;
    int ar = tid >> 2, q = tid & 3;
    int br = tid >> 4, bcn = (tid & 15) << 3;
    int lane = tid & 31, w = tid >> 5;
    int wm = w >> 2, wn = w & 3;
    int gid = lane >> 2, tig = lane & 3;

    int m0 = bm + ar;
    int bi = m0 >> 12, pix = m0 & (IMG_N - 1), py = pix >> 6, px = pix & 63;
    int it_tap = 0, it_ci = 0;
    const __half* it_ab;
    int it_aok;
    {
        int iy = py - 2, ix = px - 2;
        it_aok = ((unsigned)iy < 64u && (unsigned)ix < 64u) ? 16 : 0;
        it_ab = it_aok ? g_imgh + (size_t)((bi << 12) + (iy << 6) + ix) * DMODEL : g_imgh;
    }
    const uint32_t* it_bp = g_w2h + (size_t)br * DMODEL + bn + bcn;
    uint32_t asd0 = as_base + (uint32_t)(ar * 20 + q * 4) * 4;
    uint32_t bsd0 = bs_base + (uint32_t)(br * 136 + bcn) * 4;
    uint32_t a_lm = as_base + (uint32_t)(((wm * 32 + (lane & 15)) * 20) + ((lane >> 4) << 2)) * 4;

    float acc[2][4][4];
#pragma unroll
    for (int i = 0; i < 2; i++)
#pragma unroll
        for (int j = 0; j < 4; j++)
#pragma unroll
            for (int qq = 0; qq < 4; qq++) acc[i][j][qq] = 0.f;

    const int NTILES = K_CONV / 32;               // 600

#define CV_ISSUE(slot_)                                                          \
    {                                                                            \
        uint32_t asd_ = asd0 + (slot_) * AS64_WORDS * 4;                         \
        uint32_t bsd_ = bsd0 + (slot_) * BS_WORDS * 4;                           \
        cp16(asd_, it_ab + it_ci + q * 8, it_aok);                               \
        cp16(bsd_, it_bp, 16);                                                   \
        cp16(bsd_ + 16, it_bp + 4, 16);                                          \
        cp_commit();                                                             \
        it_bp += 16 * DMODEL;                                                    \
        it_ci += 32;                                                             \
        if (it_ci == DMODEL) {                                                   \
            it_ci = 0;                                                           \
            it_tap++;                                                            \
            if (it_tap < 25) {                                                   \
                int ky_ = it_tap / 5, kx_ = it_tap - ky_ * 5;                    \
                int iy_ = py + ky_ - 2, ix_ = px + kx_ - 2;                      \
                it_aok = ((unsigned)iy_ < 64u && (unsigned)ix_ < 64u) ? 16 : 0;  \
                it_ab = it_aok                                                   \
                    ? g_imgh + (size_t)((bi << 12) + (iy_ << 6) + ix_) * DMODEL  \
                    : g_imgh;                                                    \
            }                                                                    \
        }                                                                        \
    }

    CV_ISSUE(0);
    CV_ISSUE(1);
    CV_ISSUE(2);
    CV_ISSUE(3);

    int islot = 4, cslot = 0;
    for (int kt = 0; kt < NTILES; ++kt) {
        cp_wait3();
        __syncthreads();
        if (kt + 4 < NTILES) {
            CV_ISSUE(islot);
        } else {
            cp_commit();
        }
        if (++islot == STG) islot = 0;
        uint32_t a_lm_s = a_lm + cslot * AS64_WORDS * 4;
        const uint32_t* Bsb = (const uint32_t*)(BsB + cslot * BS_WORDS);
#pragma unroll
        for (int ks = 0; ks < 2; ++ks) {
            int k8 = ks * 8;
            uint32_t af[2][4], bf[4][2];
#pragma unroll
            for (int tm = 0; tm < 2; tm++)
                ldmatrix4(af[tm], a_lm_s + (uint32_t)(tm * 320 + k8) * 4);
#pragma unroll
            for (int tn = 0; tn < 4; tn++) {
                int cl = wn * 32 + tn * 8 + gid;
                bf[tn][0] = Bsb[(k8 + tig) * 136 + cl];
                bf[tn][1] = Bsb[(k8 + tig + 4) * 136 + cl];
            }
#pragma unroll
            for (int tm = 0; tm < 2; tm++)
#pragma unroll
                for (int tn = 0; tn < 4; tn++)
                    mma16(acc[tm][tn], af[tm], bf[tn]);
        }
        if (++cslot == STG) cslot = 0;
    }
    cp_wait0();
#pragma unroll
    for (int tm = 0; tm < 2; tm++) {
        int mm0 = bm + wm * 32 + tm * 16 + gid;
        int mm1 = mm0 + 8;
        size_t orow0 = (size_t)(((mm0 >> 12) * L_SEQ) + HEAD_ROWS + (mm0 & (IMG_N - 1))) * DMODEL;
        size_t orow1 = (size_t)(((mm1 >> 12) * L_SEQ) + HEAD_ROWS + (mm1 & (IMG_N - 1))) * DMODEL;
#pragma unroll
        for (int tn = 0; tn < 4; tn++) {
            int c = bn + wn * 32 + tn * 8 + tig * 2;
            float2 bsv = *(const float2*)&bias2[c];
            float2 x0 = *(const float2*)&x[orow0 + c];
            float2 x1 = *(const float2*)&x[orow1 + c];
            *(float2*)&out[orow0 + c] = make_float2(
                acc[tm][tn][0] + bsv.x + x0.x, acc[tm][tn][1] + bsv.y + x0.y);
            *(float2*)&out[orow1 + c] = make_float2(
                acc[tm][tn][2] + bsv.x + x1.x, acc[tm][tn][3] + bsv.y + x1.y);
        }
    }
}

// ---------------- depthwise causal conv1d + silu + fused dt/dA ----------------
__global__ void conv1d_kernel(const float* __restrict__ w, const float* __restrict__ bias,
                              const float* __restrict__ dt_bias, const float* __restrict__ A_log) {
    int row = blockIdx.x;
    int b = row / L_SEQ;
    int l = row - b * L_SEQ;
    for (int c = threadIdx.x; c < CONVDIM; c += 256) {
        float acc = bias[c];
#pragma unroll
        for (int j = 0; j < 4; j++) {
            int ll = l - 3 + j;
            if (ll >= 0)
                acc += g_zx[(size_t)(b * L_SEQ + ll) * DPROJ + DINNER + c] * w[c * 4 + j];
        }
        acc = acc / (1.f + expf(-acc));
        g_xbc[(size_t)row * CONVDIM + c] = acc;
    }
    if (threadIdx.x < NHEADS) {
        int h = threadIdx.x;
        float v = g_zx[(size_t)row * DPROJ + (DINNER + CONVDIM) + h] + dt_bias[h];
        float dtv = (v > 20.f) ? v : log1pf(expf(v));
        g_dt[row * NHEADS + h] = dtv;
        g_dA[row * NHEADS + h] = expf(-dtv * expf(A_log[h]));
    }
}

// ---------------- scan pass 1 ----------------
__global__ __launch_bounds__(64) void scan_seg_kernel(const float* __restrict__ Dskip) {
    int p = threadIdx.x;
    int seg = blockIdx.x, hh = blockIdx.y, b = blockIdx.z;
    float4 h[32];
#pragma unroll
    for (int i = 0; i < 32; i++) h[i] = make_float4(0.f, 0.f, 0.f, 0.f);
    float cum = 1.f;
    float Dh = Dskip[hh];
    size_t r0 = (size_t)b * L_SEQ + seg * TSEG;
    const float* pxb = g_xbc + r0 * CONVDIM;
    const float* pda = g_dA + r0 * NHEADS + hh;
    const float* pdt = g_dt + r0 * NHEADS + hh;
    float* py = g_y + r0 * DINNER + hh * HEADDIM + p;
    float* pc = g_cums + r0 * NHEADS + hh;
    for (int t = 0; t < TSEG; ++t) {
        float dAt = *pda;
        float dtt = *pdt;
        float xs = pxb[hh * HEADDIM + p];
        float dtx = dtt * xs;
        cum *= dAt;
        float y = Dh * xs;
        const float4* Bv = (const float4*)(pxb + DINNER);
        const float4* Cv = (const float4*)(pxb + DINNER + DSTATE);
#pragma unroll
        for (int i = 0; i < 32; i++) {
            float4 Bb = Bv[i];
            float4 Cc = Cv[i];
            h[i].x = h[i].x * dAt + dtx * Bb.x;
            h[i].y = h[i].y * dAt + dtx * Bb.y;
            h[i].z = h[i].z * dAt + dtx * Bb.z;
            h[i].w = h[i].w * dAt + dtx * Bb.w;
            y += h[i].x * Cc.x + h[i].y * Cc.y + h[i].z * Cc.z + h[i].w * Cc.w;
        }
        *py = y;
        if (p == 0) *pc = cum;
        pxb += CONVDIM; pda += NHEADS; pdt += NHEADS; py += DINNER; pc += NHEADS;
    }
    float* hs = g_hseg + (((size_t)(b * NHEADS + hh) * SEG + seg) * HEADDIM + p) * DSTATE;
#pragma unroll
    for (int i = 0; i < 32; i++) *(float4*)(hs + i * 4) = h[i];
}

// ---------------- scan pass 2 ----------------
__global__ void carry_kernel() {
    int bh = blockIdx.x;
    int b = bh / NHEADS, hh = bh - b * NHEADS;
    __shared__ float dAseg[SEG];
    if (threadIdx.x < SEG) {
        size_t t = (size_t)b * L_SEQ + (threadIdx.x + 1) * TSEG - 1;
        dAseg[threadIdx.x] = g_cums[t * NHEADS + hh];
    }
    __syncthreads();
    float* base = g_hseg + (size_t)bh * SEG * HEADDIM * DSTATE;
    for (int e = threadIdx.x; e < HEADDIM * DSTATE; e += 256) {
        float carry = 0.f;
#pragma unroll
        for (int s = 0; s < SEG; s++) {
            float* ptr = base + (size_t)s * HEADDIM * DSTATE + e;
            float tmp = *ptr;
            *ptr = carry;
            carry = dAseg[s] * carry + tmp;
        }
    }
}

// ---------------- scan pass 3 ----------------
__global__ __launch_bounds__(64) void scan_fix_kernel() {
    int p = threadIdx.x;
    int seg = blockIdx.x + 1, hh = blockIdx.y, b = blockIdx.z;
    float4 h[32];
    const float* hs = g_hseg + (((size_t)(b * NHEADS + hh) * SEG + seg) * HEADDIM + p) * DSTATE;
#pragma unroll
    for (int i = 0; i < 32; i++) h[i] = *(const float4*)(hs + i * 4);
    size_t r0 = (size_t)b * L_SEQ + seg * TSEG;
    const float* pC = g_xbc + r0 * CONVDIM + DINNER + DSTATE;
    const float* pc = g_cums + r0 * NHEADS + hh;
    float* py = g_y + r0 * DINNER + hh * HEADDIM + p;
    for (int t = 0; t < TSEG; ++t) {
        float cumt = *pc;
        float y = 0.f;
        const float4* Cv = (const float4*)pC;
#pragma unroll
        for (int i = 0; i < 32; i++) {
            float4 Cc = Cv[i];
            y += h[i].x * Cc.x + h[i].y * Cc.y + h[i].z * Cc.z + h[i].w * Cc.w;
        }
        *py += cumt * y;
        pC += CONVDIM; pc += NHEADS; py += DINNER;
    }
}

// ---------------- gate + RMSNorm -> half ----------------
__global__ void gate_rms_kernel(const float* __restrict__ norm_w) {
    int row = blockIdx.x;
    int tid = threadIdx.x;
    __shared__ float sh[DINNER];
    float ss = 0.f;
#pragma unroll
    for (int it = 0; it < 6; ++it) {
        int c = tid + it * 256;
        float z = g_zx[(size_t)row * DPROJ + c];
        float yv = g_y[(size_t)row * DINNER + c];
        float t = yv * (z / (1.f + expf(-z)));
        sh[c] = t;
        ss += t * t;
    }
    float tot = blockSum256(ss);
    float sc = rsqrtf(tot * (1.f / 1536.f) + LN_EPS);
#pragma unroll
    for (int it = 0; it < 6; ++it) {
        int c = tid + it * 256;
        g_yh[(size_t)row * DINNER + c] = __float2half_rn(sh[c] * sc * norm_w[c]);
    }
}

// ---------------- head rows: out = x + h ----------------
__global__ void head_add_kernel(const float* __restrict__ x, float* __restrict__ out) {
    int row = blockIdx.x;
    int b = row / HEAD_ROWS;
    int l = row - b * HEAD_ROWS;
    int g = (b * L_SEQ + l) * DMODEL;
    for (int c = threadIdx.x; c < DMODEL; c += 256)
        out[g + c] = x[g + c] + g_h[g + c];
}

// ---------------- launch ----------------
extern "C" void kernel_launch(void* const* d_in, const int* in_sizes, int n_in,
                              void* d_out, int out_size) {
    const float* x         = (const float*)d_in[0];
    const float* ln1_w     = (const float*)d_in[1];
    const float* ln1_b     = (const float*)d_in[2];
    const float* in_proj_w = (const float*)d_in[3];
    const float* conv1d_w  = (const float*)d_in[4];
    const float* conv1d_b  = (const float*)d_in[5];
    const float* dt_bias   = (const float*)d_in[6];
    const float* A_log     = (const float*)d_in[7];
    const float* Dskip     = (const float*)d_in[8];
    const float* norm_w    = (const float*)d_in[9];
    const float* out_proj_w= (const float*)d_in[10];
    const float* ln2_w     = (const float*)d_in[11];
    const float* ln2_b     = (const float*)d_in[12];
    const float* conv2d_w  = (const float*)d_in[13];
    const float* conv2d_b  = (const float*)d_in[14];
    float* out = (float*)d_out;

    static int smem_set = 0;
    if (!smem_set) {
        cudaFuncSetAttribute(hgemm_cp_kernel,
                             cudaFuncAttributeMaxDynamicSharedMemorySize, SMEM_BYTES);
        cudaFuncSetAttribute(hgemm64_cp_kernel,
                             cudaFuncAttributeMaxDynamicSharedMemorySize, SMEM64_BYTES);
        cudaFuncSetAttribute(conv2d_hm_kernel,
                             cudaFuncAttributeMaxDynamicSharedMemorySize, SMEM64_BYTES);
        smem_set = 1;
    }

    void *puh, *pzx, *pyh, *ph, *pw1, *pw3, *pw2th, *pw2h;
    cudaGetSymbolAddress(&puh, g_uh);
    cudaGetSymbolAddress(&pzx, g_zx);
    cudaGetSymbolAddress(&pyh, g_yh);
    cudaGetSymbolAddress(&ph, g_h);
    cudaGetSymbolAddress(&pw1, g_w1h);
    cudaGetSymbolAddress(&pw3, g_w3h);
    cudaGetSymbolAddress(&pw2th, g_w2th);
    cudaGetSymbolAddress(&pw2h, g_w2h);

    // order keeps in_proj at ncu launch #4
    ln1_kernel<<<ROWS, 256>>>(x, ln1_w, ln1_b);
    pack_pairs_kernel<<<((DMODEL / 2) * DPROJ + 255) / 256, 256>>>(
        in_proj_w, (uint32_t*)pw1, DMODEL / 2, DPROJ);
    wtrans_kernel<<<dim3(K_CONV / 32, DMODEL / 32), dim3(32, 8)>>>(conv2d_w);

    hgemm_cp_kernel<<<dim3((DPROJ + 127) / 128, ROWS / 128), 256, SMEM_BYTES>>>(
        (const __half*)puh, (const uint32_t*)pw1, (float*)pzx, ROWS, DPROJ, DMODEL);

    pack_pairs_h_kernel<<<((K_CONV / 2) * DMODEL + 255) / 256, 256>>>(
        (const __half*)pw2th, (uint32_t*)pw2h, K_CONV / 2, DMODEL);
    conv1d_kernel<<<ROWS, 256>>>(conv1d_w, conv1d_b, dt_bias, A_log);

    scan_seg_kernel<<<dim3(SEG, NHEADS, B_SZ), 64>>>(Dskip);
    carry_kernel<<<B_SZ * NHEADS, 256>>>();
    scan_fix_kernel<<<dim3(SEG - 1, NHEADS, B_SZ), 64>>>();

    gate_rms_kernel<<<ROWS, 256>>>(norm_w);
    pack_pairs_kernel<<<((DINNER / 2) * DMODEL + 255) / 256, 256>>>(
        out_proj_w, (uint32_t*)pw3, DINNER / 2, DMODEL);

    hgemm64_cp_kernel<<<dim3(DMODEL / 128, ROWS / 64), 256, SMEM64_BYTES>>>(
        (const __half*)pyh, (const uint32_t*)pw3, (float*)ph, ROWS, DMODEL, DINNER);

    head_add_kernel<<<B_SZ * HEAD_ROWS, 256>>>(x, out);
    ln2_kernel<<<B_SZ * IMG_N, 256>>>(ln2_w, ln2_b);

    conv2d_hm_kernel<<<dim3(DMODEL / 128, (B_SZ * IMG_N) / 64), 256, SMEM64_BYTES>>>(
        x, conv2d_b, out);
}

// round 17
// speedup vs baseline: 1.0519x; 1.0519x over previous
#include <cuda_runtime.h>
#include <cuda_fp16.h>
#include <math.h>
#include <stdint.h>

#define B_SZ 2
#define L_SEQ 4352
#define DMODEL 768
#define DINNER 1536
#define DSTATE 128
#define NHEADS 24
#define HEADDIM 64
#define CONVDIM 1792
#define DPROJ 3352
#define IMG_N 4096
#define ROWS (B_SZ * L_SEQ)            // 8704
#define HEAD_ROWS (L_SEQ - IMG_N)      // 256
#define LN_EPS 1e-5f
#define K_CONV (25 * DMODEL)           // 19200
#define SEG 34
#define TSEG 128                       // 34*128 = 4352

// fp16 HMMA pipeline (128-row tiles, in_proj): BK=32 halfs
#define STG 4
#define AS_WORDS (128 * 20)
#define BS_WORDS (16 * 136)
#define SMEM_BYTES (STG * (AS_WORDS + BS_WORDS) * 4)   // 75776

// 64-row tile variant (conv2d / out_proj)
#define AS64_WORDS (64 * 20)           // 1280
#define SMEM64_BYTES (STG * (AS64_WORDS + BS_WORDS) * 4)  // 55296 -> 3+ CTAs/SM

// ---------------- static scratch ----------------
__device__ __align__(16) __half g_uh[ROWS * DMODEL];
__device__ __align__(16) float g_zx[ROWS * DPROJ];
__device__ __align__(16) float g_xbc[ROWS * CONVDIM];
__device__ float g_dt[ROWS * NHEADS];
__device__ float g_dA[ROWS * NHEADS];
__device__ float g_cums[ROWS * NHEADS];
__device__ __align__(16) float g_hseg[B_SZ * NHEADS * SEG * HEADDIM * DSTATE]; // 51MB
__device__ __align__(16) float g_y[ROWS * DINNER];
__device__ __align__(16) __half g_yh[ROWS * DINNER];
__device__ __align__(16) float g_h[ROWS * DMODEL];
__device__ __align__(16) __half g_imgh[B_SZ * IMG_N * DMODEL];
__device__ __align__(16) __half g_w2th[K_CONV * DMODEL];
__device__ __align__(16) uint32_t g_w2h[(K_CONV / 2) * DMODEL];
__device__ __align__(16) uint32_t g_w1h[(DMODEL / 2) * DPROJ];
__device__ __align__(16) uint32_t g_w3h[(DINNER / 2) * DMODEL];

// ---------------- helpers ----------------
__device__ __forceinline__ float blockSum256(float v) {
    __shared__ float sh[8];
    __syncthreads();
#pragma unroll
    for (int o = 16; o; o >>= 1) v += __shfl_xor_sync(0xffffffffu, v, o);
    if ((threadIdx.x & 31) == 0) sh[threadIdx.x >> 5] = v;
    __syncthreads();
    float tot = 0.f;
#pragma unroll
    for (int i = 0; i < 8; i++) tot += sh[i];
    return tot;
}

__device__ __forceinline__ void mma16(float* c, const uint32_t* a, const uint32_t* b) {
    asm("mma.sync.aligned.m16n8k16.row.col.f32.f16.f16.f32 "
        "{%0,%1,%2,%3},{%4,%5,%6,%7},{%8,%9},{%0,%1,%2,%3};"
        : "+f"(c[0]), "+f"(c[1]), "+f"(c[2]), "+f"(c[3])
        : "r"(a[0]), "r"(a[1]), "r"(a[2]), "r"(a[3]), "r"(b[0]), "r"(b[1]));
}

__device__ __forceinline__ void ldmatrix4(uint32_t* r, uint32_t addr) {
    asm volatile("ldmatrix.sync.aligned.m8n8.x4.shared.b16 {%0,%1,%2,%3}, [%4];"
                 : "=r"(r[0]), "=r"(r[1]), "=r"(r[2]), "=r"(r[3]) : "r"(addr));
}

__device__ __forceinline__ void cp16(uint32_t dst, const void* src, int srcbytes) {
    asm volatile("cp.async.cg.shared.global [%0], [%1], 16, %2;"
                 :: "r"(dst), "l"(src), "r"(srcbytes));
}
__device__ __forceinline__ void cp_commit() { asm volatile("cp.async.commit_group;"); }
__device__ __forceinline__ void cp_wait2() { asm volatile("cp.async.wait_group 2;"); }
__device__ __forceinline__ void cp_wait0() { asm volatile("cp.async.wait_group 0;"); }

// ---------------- pack fp32 [K][N] -> half2 k-pairs [K/2][N] ----------------
__global__ void pack_pairs_kernel(const float* __restrict__ src, uint32_t* __restrict__ dst,
                                  int K2, int N) {
    int i = blockIdx.x * 256 + threadIdx.x;
    if (i >= K2 * N) return;
    int k2 = i / N, n = i - k2 * N;
    __half lo = __float2half_rn(src[(size_t)(2 * k2) * N + n]);
    __half hi = __float2half_rn(src[(size_t)(2 * k2 + 1) * N + n]);
    dst[i] = (uint32_t)__half_as_ushort(lo) | ((uint32_t)__half_as_ushort(hi) << 16);
}

// ---------------- pack half [K][N] -> half2 k-pairs [K/2][N] ----------------
__global__ void pack_pairs_h_kernel(const __half* __restrict__ src, uint32_t* __restrict__ dst,
                                    int K2, int N) {
    int i = blockIdx.x * 256 + threadIdx.x;
    if (i >= K2 * N) return;
    int k2 = i / N, n = i - k2 * N;
    uint16_t lo = __half_as_ushort(src[(size_t)(2 * k2) * N + n]);
    uint16_t hi = __half_as_ushort(src[(size_t)(2 * k2 + 1) * N + n]);
    dst[i] = (uint32_t)lo | ((uint32_t)hi << 16);
}

// ---------------- conv2d weight transpose -> half ----------------
__global__ void wtrans_kernel(const float* __restrict__ w2) {
    __shared__ float tile[32][33];
    int k0 = blockIdx.x * 32, c0 = blockIdx.y * 32;
    int tx = threadIdx.x, ty = threadIdx.y;
#pragma unroll
    for (int i = 0; i < 4; i++)
        tile[ty + 8 * i][tx] = w2[(size_t)(c0 + ty + 8 * i) * K_CONV + k0 + tx];
    __syncthreads();
#pragma unroll
    for (int i = 0; i < 4; i++) {
        int k = k0 + ty + 8 * i;
        int tap = k % 25, ci = k / 25;
        g_w2th[(size_t)(tap * DMODEL + ci) * DMODEL + c0 + tx] =
            __float2half_rn(tile[tx][ty + 8 * i]);
    }
}

// ---------------- LayerNorm 1 ----------------
__global__ void ln1_kernel(const float* __restrict__ x, const float* __restrict__ w,
                           const float* __restrict__ b) {
    int row = blockIdx.x;
    int tid = threadIdx.x;
    const float* xr = x + row * DMODEL;
    float v0 = xr[tid], v1 = xr[tid + 256], v2 = xr[tid + 512];
    float mean = blockSum256(v0 + v1 + v2) * (1.f / 768.f);
    float d0 = v0 - mean, d1 = v1 - mean, d2 = v2 - mean;
    float var = blockSum256(d0 * d0 + d1 * d1 + d2 * d2) * (1.f / 768.f);
    float rs = rsqrtf(var + LN_EPS);
    __half* o = g_uh + (size_t)row * DMODEL;
    o[tid]       = __float2half_rn(d0 * rs * w[tid]       + b[tid]);
    o[tid + 256] = __float2half_rn(d1 * rs * w[tid + 256] + b[tid + 256]);
    o[tid + 512] = __float2half_rn(d2 * rs * w[tid + 512] + b[tid + 512]);
}

// ---------------- LayerNorm 2 ----------------
__global__ void ln2_kernel(const float* __restrict__ w, const float* __restrict__ b) {
    int m = blockIdx.x;
    int tid = threadIdx.x;
    int bb = m >> 12, pix = m & (IMG_N - 1);
    const float* xr = g_h + (size_t)(bb * L_SEQ + HEAD_ROWS + pix) * DMODEL;
    float v0 = xr[tid], v1 = xr[tid + 256], v2 = xr[tid + 512];
    float mean = blockSum256(v0 + v1 + v2) * (1.f / 768.f);
    float d0 = v0 - mean, d1 = v1 - mean, d2 = v2 - mean;
    float var = blockSum256(d0 * d0 + d1 * d1 + d2 * d2) * (1.f / 768.f);
    float rs = rsqrtf(var + LN_EPS);
    __half* o = g_imgh + (size_t)m * DMODEL;
    o[tid]       = __float2half_rn(d0 * rs * w[tid]       + b[tid]);
    o[tid + 256] = __float2half_rn(d1 * rs * w[tid + 256] + b[tid + 256]);
    o[tid + 512] = __float2half_rn(d2 * rs * w[tid + 512] + b[tid + 512]);
}

// ============================================================================
// fp16 HMMA GEMM, 128-row tile (in_proj). Round-10/14 proven config.
// ============================================================================
__global__ __launch_bounds__(256) void hgemm_cp_kernel(
    const __half* __restrict__ A, const uint32_t* __restrict__ Bp,
    float* __restrict__ C, int M, int N, int K) {
    extern __shared__ float smem[];
    float* AsB = smem;
    float* BsB = smem + STG * AS_WORDS;
    uint32_t as_base = (uint32_t)__cvta_generic_to_shared(AsB);
    uint32_t bs_base = (uint32_t)__cvta_generic_to_shared(BsB);
    int tid = threadIdx.x;
    int bm = blockIdx.y * 128, bn = blockIdx.x * 128;
    int ar = tid >> 1, p = tid & 1;
    int br = tid >> 4, bcn = (tid & 15) << 3;
    int lane = tid & 31, w = tid >> 5;
    int wm = w >> 2, wn = w & 3;
    int gid = lane >> 2, tig = lane & 3;

    int colb = bn + bcn;
    bool bok = colb < N;
    int bsrc = bok ? 16 : 0;
    const __half* aptr = A + (size_t)(bm + ar) * K + p * 16;
    const uint32_t* bptr = Bp + (size_t)br * N + (bok ? colb : 0);
    uint32_t asd0 = as_base + (uint32_t)(ar * 20 + p * 8) * 4;
    uint32_t bsd0 = bs_base + (uint32_t)(br * 136 + bcn) * 4;
    uint32_t a_lm = as_base + (uint32_t)(((wm * 64 + (lane & 15)) * 20) + ((lane >> 4) << 2)) * 4;

    float acc[4][4][4];
#pragma unroll
    for (int i = 0; i < 4; i++)
#pragma unroll
        for (int j = 0; j < 4; j++)
#pragma unroll
            for (int q = 0; q < 4; q++) acc[i][j][q] = 0.f;

    int ntiles = K >> 5;
#pragma unroll 1
    for (int s = 0; s < 3; ++s) {
        uint32_t asd = asd0 + s * AS_WORDS * 4;
        uint32_t bsd = bsd0 + s * BS_WORDS * 4;
        int ka = s << 5, kb = s << 4;
        cp16(asd, aptr + ka, 16);
        cp16(asd + 16, aptr + ka + 8, 16);
        cp16(bsd, bptr + (size_t)kb * N, bsrc);
        cp16(bsd + 16, bptr + (size_t)kb * N + 4, bsrc);
        cp_commit();
    }

    for (int kt = 0; kt < ntiles; ++kt) {
        cp_wait2();
        __syncthreads();
        if (kt + 3 < ntiles) {
            int slotn = (kt + 3) & 3;
            uint32_t asd = asd0 + slotn * AS_WORDS * 4;
            uint32_t bsd = bsd0 + slotn * BS_WORDS * 4;
            int ka = (kt + 3) << 5, kb = (kt + 3) << 4;
            cp16(asd, aptr + ka, 16);
            cp16(asd + 16, aptr + ka + 8, 16);
            cp16(bsd, bptr + (size_t)kb * N, bsrc);
            cp16(bsd + 16, bptr + (size_t)kb * N + 4, bsrc);
        }
        cp_commit();
        int slot = kt & 3;
        uint32_t a_lm_s = a_lm + slot * AS_WORDS * 4;
        const uint32_t* Bsb = (const uint32_t*)(BsB + slot * BS_WORDS);
#pragma unroll
        for (int ks = 0; ks < 2; ++ks) {
            int k8 = ks * 8;
            uint32_t af[4][4], bf[4][2];
#pragma unroll
            for (int tm = 0; tm < 4; tm++)
                ldmatrix4(af[tm], a_lm_s + (uint32_t)(tm * 320 + k8) * 4);
#pragma unroll
            for (int tn = 0; tn < 4; tn++) {
                int cl = wn * 32 + tn * 8 + gid;
                bf[tn][0] = Bsb[(k8 + tig) * 136 + cl];
                bf[tn][1] = Bsb[(k8 + tig + 4) * 136 + cl];
            }
#pragma unroll
            for (int tm = 0; tm < 4; tm++)
#pragma unroll
                for (int tn = 0; tn < 4; tn++)
                    mma16(acc[tm][tn], af[tm], bf[tn]);
        }
    }
    cp_wait0();
#pragma unroll
    for (int tm = 0; tm < 4; tm++) {
        int r0 = bm + wm * 64 + tm * 16 + gid;
#pragma unroll
        for (int tn = 0; tn < 4; tn++) {
            int c = bn + wn * 32 + tn * 8 + tig * 2;
            if (c < N) {
                *(float2*)&C[(size_t)r0 * N + c]       = make_float2(acc[tm][tn][0], acc[tm][tn][1]);
                *(float2*)&C[(size_t)(r0 + 8) * N + c] = make_float2(acc[tm][tn][2], acc[tm][tn][3]);
            }
        }
    }
}

// ============================================================================
// fp16 HMMA GEMM, 64-row tile (out_proj). 8 warps 2x4, warp tile 32x32.
// ============================================================================
__global__ __launch_bounds__(256) void hgemm64_cp_kernel(
    const __half* __restrict__ A, const uint32_t* __restrict__ Bp,
    float* __restrict__ C, int M, int N, int K) {
    extern __shared__ float smem[];
    float* AsB = smem;
    float* BsB = smem + STG * AS64_WORDS;
    uint32_t as_base = (uint32_t)__cvta_generic_to_shared(AsB);
    uint32_t bs_base = (uint32_t)__cvta_generic_to_shared(BsB);
    int tid = threadIdx.x;
    int bm = blockIdx.y * 64, bn = blockIdx.x * 128;
    int ar = tid >> 2, q = tid & 3;
    int br = tid >> 4, bcn = (tid & 15) << 3;
    int lane = tid & 31, w = tid >> 5;
    int wm = w >> 2, wn = w & 3;
    int gid = lane >> 2, tig = lane & 3;

    int colb = bn + bcn;
    bool bok = colb < N;
    int bsrc = bok ? 16 : 0;
    const __half* aptr = A + (size_t)(bm + ar) * K + q * 8;
    const uint32_t* bptr = Bp + (size_t)br * N + (bok ? colb : 0);
    uint32_t asd0 = as_base + (uint32_t)(ar * 20 + q * 4) * 4;
    uint32_t bsd0 = bs_base + (uint32_t)(br * 136 + bcn) * 4;
    uint32_t a_lm = as_base + (uint32_t)(((wm * 32 + (lane & 15)) * 20) + ((lane >> 4) << 2)) * 4;

    float acc[2][4][4];
#pragma unroll
    for (int i = 0; i < 2; i++)
#pragma unroll
        for (int j = 0; j < 4; j++)
#pragma unroll
            for (int qq = 0; qq < 4; qq++) acc[i][j][qq] = 0.f;

    int ntiles = K >> 5;
#pragma unroll 1
    for (int s = 0; s < 3; ++s) {
        uint32_t asd = asd0 + s * AS64_WORDS * 4;
        uint32_t bsd = bsd0 + s * BS_WORDS * 4;
        int ka = s << 5, kb = s << 4;
        cp16(asd, aptr + ka, 16);
        cp16(bsd, bptr + (size_t)kb * N, bsrc);
        cp16(bsd + 16, bptr + (size_t)kb * N + 4, bsrc);
        cp_commit();
    }

    for (int kt = 0; kt < ntiles; ++kt) {
        cp_wait2();
        __syncthreads();
        if (kt + 3 < ntiles) {
            int slotn = (kt + 3) & 3;
            uint32_t asd = asd0 + slotn * AS64_WORDS * 4;
            uint32_t bsd = bsd0 + slotn * BS_WORDS * 4;
            int ka = (kt + 3) << 5, kb = (kt + 3) << 4;
            cp16(asd, aptr + ka, 16);
            cp16(bsd, bptr + (size_t)kb * N, bsrc);
            cp16(bsd + 16, bptr + (size_t)kb * N + 4, bsrc);
        }
        cp_commit();
        int slot = kt & 3;
        uint32_t a_lm_s = a_lm + slot * AS64_WORDS * 4;
        const uint32_t* Bsb = (const uint32_t*)(BsB + slot * BS_WORDS);
#pragma unroll
        for (int ks = 0; ks < 2; ++ks) {
            int k8 = ks * 8;
            uint32_t af[2][4], bf[4][2];
#pragma unroll
            for (int tm = 0; tm < 2; tm++)
                ldmatrix4(af[tm], a_lm_s + (uint32_t)(tm * 320 + k8) * 4);
#pragma unroll
            for (int tn = 0; tn < 4; tn++) {
                int cl = wn * 32 + tn * 8 + gid;
                bf[tn][0] = Bsb[(k8 + tig) * 136 + cl];
                bf[tn][1] = Bsb[(k8 + tig + 4) * 136 + cl];
            }
#pragma unroll
            for (int tm = 0; tm < 2; tm++)
#pragma unroll
                for (int tn = 0; tn < 4; tn++)
                    mma16(acc[tm][tn], af[tm], bf[tn]);
        }
    }
    cp_wait0();
#pragma unroll
    for (int tm = 0; tm < 2; tm++) {
        int r0 = bm + wm * 32 + tm * 16 + gid;
#pragma unroll
        for (int tn = 0; tn < 4; tn++) {
            int c = bn + wn * 32 + tn * 8 + tig * 2;
            if (c < N) {
                *(float2*)&C[(size_t)r0 * N + c]       = make_float2(acc[tm][tn][0], acc[tm][tn][1]);
                *(float2*)&C[(size_t)(r0 + 8) * N + c] = make_float2(acc[tm][tn][2], acc[tm][tn][3]);
            }
        }
    }
}

// ============================================================================
// conv2d 5x5 SAME implicit GEMM, 64-row tile + bias + residual.
// ============================================================================
__global__ __launch_bounds__(256) void conv2d_hm_kernel(
    const float* __restrict__ x, const float* __restrict__ bias2,
    float* __restrict__ out) {
    extern __shared__ float smem[];
    float* AsB = smem;
    float* BsB = smem + STG * AS64_WORDS;
    uint32_t as_base = (uint32_t)__cvta_generic_to_shared(AsB);
    uint32_t bs_base = (uint32_t)__cvta_generic_to_shared(BsB);
    int tid = threadIdx.x;
    int bm = blockIdx.y * 64, bn = blockIdx.x * 128;
    int ar = tid >> 2, q = tid & 3;
    int br = tid >> 4, bcn = (tid & 15) << 3;
    int lane = tid & 31, w = tid >> 5;
    int wm = w >> 2, wn = w & 3;
    int gid = lane >> 2, tig = lane & 3;

    int m0 = bm + ar;
    int bi = m0 >> 12, pix = m0 & (IMG_N - 1), py = pix >> 6, px = pix & 63;
    int it_tap = 0, it_ci = 0;
    const __half* it_ab;
    int it_aok;
    {
        int iy = py - 2, ix = px - 2;
        it_aok = ((unsigned)iy < 64u && (unsigned)ix < 64u) ? 16 : 0;
        it_ab = it_aok ? g_imgh + (size_t)((bi << 12) + (iy << 6) + ix) * DMODEL : g_imgh;
    }
    const uint32_t* it_bp = g_w2h + (size_t)br * DMODEL + bn + bcn;
    uint32_t asd0 = as_base + (uint32_t)(ar * 20 + q * 4) * 4;
    uint32_t bsd0 = bs_base + (uint32_t)(br * 136 + bcn) * 4;
    uint32_t a_lm = as_base + (uint32_t)(((wm * 32 + (lane & 15)) * 20) + ((lane >> 4) << 2)) * 4;

    float acc[2][4][4];
#pragma unroll
    for (int i = 0; i < 2; i++)
#pragma unroll
        for (int j = 0; j < 4; j++)
#pragma unroll
            for (int qq = 0; qq < 4; qq++) acc[i][j][qq] = 0.f;

    const int NTILES = K_CONV / 32;               // 600

#define CV_ISSUE(slot_)                                                          \
    {                                                                            \
        uint32_t asd_ = asd0 + (slot_) * AS64_WORDS * 4;                         \
        uint32_t bsd_ = bsd0 + (slot_) * BS_WORDS * 4;                           \
        cp16(asd_, it_ab + it_ci + q * 8, it_aok);                               \
        cp16(bsd_, it_bp, 16);                                                   \
        cp16(bsd_ + 16, it_bp + 4, 16);                                          \
        cp_commit();                                                             \
        it_bp += 16 * DMODEL;                                                    \
        it_ci += 32;                                                             \
        if (it_ci == DMODEL) {                                                   \
            it_ci = 0;                                                           \
            it_tap++;                                                            \
            if (it_tap < 25) {                                                   \
                int ky_ = it_tap / 5, kx_ = it_tap - ky_ * 5;                    \
                int iy_ = py + ky_ - 2, ix_ = px + kx_ - 2;                      \
                it_aok = ((unsigned)iy_ < 64u && (unsigned)ix_ < 64u) ? 16 : 0;  \
                it_ab = it_aok                                                   \
                    ? g_imgh + (size_t)((bi << 12) + (iy_ << 6) + ix_) * DMODEL  \
                    : g_imgh;                                                    \
            }                                                                    \
        }                                                                        \
    }

    CV_ISSUE(0);
    CV_ISSUE(1);
    CV_ISSUE(2);

    for (int kt = 0; kt < NTILES; ++kt) {
        cp_wait2();
        __syncthreads();
        if (kt + 3 < NTILES) {
            CV_ISSUE((kt + 3) & 3);
        } else {
            cp_commit();
        }
        int slot = kt & 3;
        uint32_t a_lm_s = a_lm + slot * AS64_WORDS * 4;
        const uint32_t* Bsb = (const uint32_t*)(BsB + slot * BS_WORDS);
#pragma unroll
        for (int ks = 0; ks < 2; ++ks) {
            int k8 = ks * 8;
            uint32_t af[2][4], bf[4][2];
#pragma unroll
            for (int tm = 0; tm < 2; tm++)
                ldmatrix4(af[tm], a_lm_s + (uint32_t)(tm * 320 + k8) * 4);
#pragma unroll
            for (int tn = 0; tn < 4; tn++) {
                int cl = wn * 32 + tn * 8 + gid;
                bf[tn][0] = Bsb[(k8 + tig) * 136 + cl];
                bf[tn][1] = Bsb[(k8 + tig + 4) * 136 + cl];
            }
#pragma unroll
            for (int tm = 0; tm < 2; tm++)
#pragma unroll
                for (int tn = 0; tn < 4; tn++)
                    mma16(acc[tm][tn], af[tm], bf[tn]);
        }
    }
    cp_wait0();
#pragma unroll
    for (int tm = 0; tm < 2; tm++) {
        int mm0 = bm + wm * 32 + tm * 16 + gid;
        int mm1 = mm0 + 8;
        size_t orow0 = (size_t)(((mm0 >> 12) * L_SEQ) + HEAD_ROWS + (mm0 & (IMG_N - 1))) * DMODEL;
        size_t orow1 = (size_t)(((mm1 >> 12) * L_SEQ) + HEAD_ROWS + (mm1 & (IMG_N - 1))) * DMODEL;
#pragma unroll
        for (int tn = 0; tn < 4; tn++) {
            int c = bn + wn * 32 + tn * 8 + tig * 2;
            float2 bsv = *(const float2*)&bias2[c];
            float2 x0 = *(const float2*)&x[orow0 + c];
            float2 x1 = *(const float2*)&x[orow1 + c];
            *(float2*)&out[orow0 + c] = make_float2(
                acc[tm][tn][0] + bsv.x + x0.x, acc[tm][tn][1] + bsv.y + x0.y);
            *(float2*)&out[orow1 + c] = make_float2(
                acc[tm][tn][2] + bsv.x + x1.x, acc[tm][tn][3] + bsv.y + x1.y);
        }
    }
}

// ---------------- conv1d (tiled, 8 rows x 256 cols per block) + dt/dA -------
// grid (ROWS/8, CONVDIM/256); 11-row smem halo; read amp 4x -> 1.375x.
__global__ __launch_bounds__(256) void conv1d_kernel(
    const float* __restrict__ w, const float* __restrict__ bias,
    const float* __restrict__ dt_bias, const float* __restrict__ A_log) {
    __shared__ float sx[11][256];
    int tid = threadIdx.x;
    int blk = blockIdx.x;
    int b = blk / (L_SEQ / 8);
    int l0 = (blk - b * (L_SEQ / 8)) * 8;
    int c0 = blockIdx.y * 256;
    int c = c0 + tid;

    // load 11 rows (l0-3 .. l0+7) of this column slice
#pragma unroll
    for (int i = 0; i < 11; i++) {
        int l = l0 - 3 + i;
        sx[i][tid] = (l >= 0)
            ? g_zx[(size_t)(b * L_SEQ + l) * DPROJ + DINNER + c]
            : 0.f;
    }
    __syncthreads();

    float w0 = w[c * 4], w1 = w[c * 4 + 1], w2 = w[c * 4 + 2], w3 = w[c * 4 + 3];
    float bs = bias[c];
#pragma unroll
    for (int rl = 0; rl < 8; rl++) {
        float acc = bs;
        acc += sx[rl][tid] * w0;
        acc += sx[rl + 1][tid] * w1;
        acc += sx[rl + 2][tid] * w2;
        acc += sx[rl + 3][tid] * w3;
        acc = acc / (1.f + expf(-acc));
        g_xbc[(size_t)(b * L_SEQ + l0 + rl) * CONVDIM + c] = acc;
    }

    if (blockIdx.y == 0 && tid < 8 * NHEADS) {
        int rl = tid / NHEADS, h = tid - rl * NHEADS;
        int row = b * L_SEQ + l0 + rl;
        float v = g_zx[(size_t)row * DPROJ + (DINNER + CONVDIM) + h] + dt_bias[h];
        float dtv = (v > 20.f) ? v : log1pf(expf(v));
        g_dt[row * NHEADS + h] = dtv;
        g_dA[row * NHEADS + h] = expf(-dtv * expf(A_log[h]));
    }
}

// ---------------- scan pass 1 ----------------
__global__ __launch_bounds__(64) void scan_seg_kernel(const float* __restrict__ Dskip) {
    int p = threadIdx.x;
    int seg = blockIdx.x, hh = blockIdx.y, b = blockIdx.z;
    float4 h[32];
#pragma unroll
    for (int i = 0; i < 32; i++) h[i] = make_float4(0.f, 0.f, 0.f, 0.f);
    float cum = 1.f;
    float Dh = Dskip[hh];
    size_t r0 = (size_t)b * L_SEQ + seg * TSEG;
    const float* pxb = g_xbc + r0 * CONVDIM;
    const float* pda = g_dA + r0 * NHEADS + hh;
    const float* pdt = g_dt + r0 * NHEADS + hh;
    float* py = g_y + r0 * DINNER + hh * HEADDIM + p;
    float* pc = g_cums + r0 * NHEADS + hh;
    for (int t = 0; t < TSEG; ++t) {
        float dAt = *pda;
        float dtt = *pdt;
        float xs = pxb[hh * HEADDIM + p];
        float dtx = dtt * xs;
        cum *= dAt;
        float y = Dh * xs;
        const float4* Bv = (const float4*)(pxb + DINNER);
        const float4* Cv = (const float4*)(pxb + DINNER + DSTATE);
#pragma unroll
        for (int i = 0; i < 32; i++) {
            float4 Bb = Bv[i];
            float4 Cc = Cv[i];
            h[i].x = h[i].x * dAt + dtx * Bb.x;
            h[i].y = h[i].y * dAt + dtx * Bb.y;
            h[i].z = h[i].z * dAt + dtx * Bb.z;
            h[i].w = h[i].w * dAt + dtx * Bb.w;
            y += h[i].x * Cc.x + h[i].y * Cc.y + h[i].z * Cc.z + h[i].w * Cc.w;
        }
        *py = y;
        if (p == 0) *pc = cum;
        pxb += CONVDIM; pda += NHEADS; pdt += NHEADS; py += DINNER; pc += NHEADS;
    }
    float* hs = g_hseg + (((size_t)(b * NHEADS + hh) * SEG + seg) * HEADDIM + p) * DSTATE;
#pragma unroll
    for (int i = 0; i < 32; i++) *(float4*)(hs + i * 4) = h[i];
}

// ---------------- scan pass 2 ----------------
__global__ void carry_kernel() {
    int bh = blockIdx.x;
    int b = bh / NHEADS, hh = bh - b * NHEADS;
    __shared__ float dAseg[SEG];
    if (threadIdx.x < SEG) {
        size_t t = (size_t)b * L_SEQ + (threadIdx.x + 1) * TSEG - 1;
        dAseg[threadIdx.x] = g_cums[t * NHEADS + hh];
    }
    __syncthreads();
    float* base = g_hseg + (size_t)bh * SEG * HEADDIM * DSTATE;
    for (int e = threadIdx.x; e < HEADDIM * DSTATE; e += 256) {
        float carry = 0.f;
#pragma unroll
        for (int s = 0; s < SEG; s++) {
            float* ptr = base + (size_t)s * HEADDIM * DSTATE + e;
            float tmp = *ptr;
            *ptr = carry;
            carry = dAseg[s] * carry + tmp;
        }
    }
}

// ---------------- scan pass 3 ----------------
__global__ __launch_bounds__(64) void scan_fix_kernel() {
    int p = threadIdx.x;
    int seg = blockIdx.x + 1, hh = blockIdx.y, b = blockIdx.z;
    float4 h[32];
    const float* hs = g_hseg + (((size_t)(b * NHEADS + hh) * SEG + seg) * HEADDIM + p) * DSTATE;
#pragma unroll
    for (int i = 0; i < 32; i++) h[i] = *(const float4*)(hs + i * 4);
    size_t r0 = (size_t)b * L_SEQ + seg * TSEG;
    const float* pC = g_xbc + r0 * CONVDIM + DINNER + DSTATE;
    const float* pc = g_cums + r0 * NHEADS + hh;
    float* py = g_y + r0 * DINNER + hh * HEADDIM + p;
    for (int t = 0; t < TSEG; ++t) {
        float cumt = *pc;
        float y = 0.f;
        const float4* Cv = (const float4*)pC;
#pragma unroll
        for (int i = 0; i < 32; i++) {
            float4 Cc = Cv[i];
            y += h[i].x * Cc.x + h[i].y * Cc.y + h[i].z * Cc.z + h[i].w * Cc.w;
        }
        *py += cumt * y;
        pC += CONVDIM; pc += NHEADS; py += DINNER;
    }
}

// ---------------- gate + RMSNorm -> half ----------------
__global__ void gate_rms_kernel(const float* __restrict__ norm_w) {
    int row = blockIdx.x;
    int tid = threadIdx.x;
    __shared__ float sh[DINNER];
    float ss = 0.f;
#pragma unroll
    for (int it = 0; it < 6; ++it) {
        int c = tid + it * 256;
        float z = g_zx[(size_t)row * DPROJ + c];
        float yv = g_y[(size_t)row * DINNER + c];
        float t = yv * (z / (1.f + expf(-z)));
        sh[c] = t;
        ss += t * t;
    }
    float tot = blockSum256(ss);
    float sc = rsqrtf(tot * (1.f / 1536.f) + LN_EPS);
#pragma unroll
    for (int it = 0; it < 6; ++it) {
        int c = tid + it * 256;
        g_yh[(size_t)row * DINNER + c] = __float2half_rn(sh[c] * sc * norm_w[c]);
    }
}

// ---------------- head rows: out = x + h ----------------
__global__ void head_add_kernel(const float* __restrict__ x, float* __restrict__ out) {
    int row = blockIdx.x;
    int b = row / HEAD_ROWS;
    int l = row - b * HEAD_ROWS;
    int g = (b * L_SEQ + l) * DMODEL;
    for (int c = threadIdx.x; c < DMODEL; c += 256)
        out[g + c] = x[g + c] + g_h[g + c];
}

// ---------------- launch ----------------
extern "C" void kernel_launch(void* const* d_in, const int* in_sizes, int n_in,
                              void* d_out, int out_size) {
    const float* x         = (const float*)d_in[0];
    const float* ln1_w     = (const float*)d_in[1];
    const float* ln1_b     = (const float*)d_in[2];
    const float* in_proj_w = (const float*)d_in[3];
    const float* conv1d_w  = (const float*)d_in[4];
    const float* conv1d_b  = (const float*)d_in[5];
    const float* dt_bias   = (const float*)d_in[6];
    const float* A_log     = (const float*)d_in[7];
    const float* Dskip     = (const float*)d_in[8];
    const float* norm_w    = (const float*)d_in[9];
    const float* out_proj_w= (const float*)d_in[10];
    const float* ln2_w     = (const float*)d_in[11];
    const float* ln2_b     = (const float*)d_in[12];
    const float* conv2d_w  = (const float*)d_in[13];
    const float* conv2d_b  = (const float*)d_in[14];
    float* out = (float*)d_out;

    static int smem_set = 0;
    if (!smem_set) {
        cudaFuncSetAttribute(hgemm_cp_kernel,
                             cudaFuncAttributeMaxDynamicSharedMemorySize, SMEM_BYTES);
        cudaFuncSetAttribute(hgemm64_cp_kernel,
                             cudaFuncAttributeMaxDynamicSharedMemorySize, SMEM64_BYTES);
        cudaFuncSetAttribute(conv2d_hm_kernel,
                             cudaFuncAttributeMaxDynamicSharedMemorySize, SMEM64_BYTES);
        smem_set = 1;
    }

    void *puh, *pzx, *pyh, *ph, *pw1, *pw3, *pw2th, *pw2h;
    cudaGetSymbolAddress(&puh, g_uh);
    cudaGetSymbolAddress(&pzx, g_zx);
    cudaGetSymbolAddress(&pyh, g_yh);
    cudaGetSymbolAddress(&ph, g_h);
    cudaGetSymbolAddress(&pw1, g_w1h);
    cudaGetSymbolAddress(&pw3, g_w3h);
    cudaGetSymbolAddress(&pw2th, g_w2th);
    cudaGetSymbolAddress(&pw2h, g_w2h);

    // order keeps in_proj at ncu launch #4
    ln1_kernel<<<ROWS, 256>>>(x, ln1_w, ln1_b);
    pack_pairs_kernel<<<((DMODEL / 2) * DPROJ + 255) / 256, 256>>>(
        in_proj_w, (uint32_t*)pw1, DMODEL / 2, DPROJ);
    wtrans_kernel<<<dim3(K_CONV / 32, DMODEL / 32), dim3(32, 8)>>>(conv2d_w);

    hgemm_cp_kernel<<<dim3((DPROJ + 127) / 128, ROWS / 128), 256, SMEM_BYTES>>>(
        (const __half*)puh, (const uint32_t*)pw1, (float*)pzx, ROWS, DPROJ, DMODEL);

    pack_pairs_h_kernel<<<((K_CONV / 2) * DMODEL + 255) / 256, 256>>>(
        (const __half*)pw2th, (uint32_t*)pw2h, K_CONV / 2, DMODEL);
    conv1d_kernel<<<dim3(ROWS / 8, CONVDIM / 256), 256>>>(
        conv1d_w, conv1d_b, dt_bias, A_log);

    scan_seg_kernel<<<dim3(SEG, NHEADS, B_SZ), 64>>>(Dskip);
    carry_kernel<<<B_SZ * NHEADS, 256>>>();
    scan_fix_kernel<<<dim3(SEG - 1, NHEADS, B_SZ), 64>>>();

    gate_rms_kernel<<<ROWS, 256>>>(norm_w);
    pack_pairs_kernel<<<((DINNER / 2) * DMODEL + 255) / 256, 256>>>(
        out_proj_w, (uint32_t*)pw3, DINNER / 2, DMODEL);

    hgemm64_cp_kernel<<<dim3(DMODEL / 128, ROWS / 64), 256, SMEM64_BYTES>>>(
        (const __half*)pyh, (const uint32_t*)pw3, (float*)ph, ROWS, DMODEL, DINNER);

    head_add_kernel<<<B_SZ * HEAD_ROWS, 256>>>(x, out);
    ln2_kernel<<<B_SZ * IMG_N, 256>>>(ln2_w, ln2_b);

    conv2d_hm_kernel<<<dim3(DMODEL / 128, (B_SZ * IMG_N) / 64), 256, SMEM64_BYTES>>>(
        x, conv2d_b, out);
}